// round 16
// baseline (speedup 1.0000x reference)
#include <cuda_runtime.h>

#define BB 128
#define NM 128

__device__ __forceinline__ unsigned f2tf(float x) {
    unsigned u; asm("cvt.rna.tf32.f32 %0, %1;" : "=r"(u) : "f"(x)); return u;
}
__device__ __forceinline__ void mma8(float& d0, float& d1, float& d2, float& d3,
                                     unsigned a0, unsigned a1, unsigned a2, unsigned a3,
                                     unsigned b0, unsigned b1) {
    asm("mma.sync.aligned.m16n8k8.row.col.f32.tf32.tf32.f32 "
        "{%0,%1,%2,%3},{%4,%5,%6,%7},{%8,%9},{%0,%1,%2,%3};"
        : "+f"(d0), "+f"(d1), "+f"(d2), "+f"(d3)
        : "r"(a0), "r"(a1), "r"(a2), "r"(a3), "r"(b0), "r"(b1));
}

// ---------------------------------------------------------------------------
// Fused kernel, R15 structure with weight fragments moved from registers to
// per-lane smem (2x LDS.128 per (stage,nt)) to cut regs ~254 -> ~150 and
// raise occupancy 2 -> 3 blocks/SM.
// ---------------------------------------------------------------------------
__global__ __launch_bounds__(128) void k_fused(
    const float* __restrict__ x_label, const float* __restrict__ x_object,
    const float* __restrict__ template_xyz,
    const float* __restrict__ mlp_w1, const float* __restrict__ mlp_s1,
    const float* __restrict__ mlp_t1, const float* __restrict__ mlp_w2,
    const float* __restrict__ mlp_s2, const float* __restrict__ mlp_t2,
    const float* __restrict__ gw_w1, const float* __restrict__ gw_b1,
    const float* __restrict__ gw_s,  const float* __restrict__ gw_t,
    const float* __restrict__ gw_w2, const float* __restrict__ gw_b2,
    const float* __restrict__ gm_w1, const float* __restrict__ gm_s1,
    const float* __restrict__ gm_t1, const float* __restrict__ gm_w2,
    const float* __restrict__ gm_s2, const float* __restrict__ gm_t2,
    const float* __restrict__ fl_w1, const float* __restrict__ fl_s1,
    const float* __restrict__ fl_t1, const float* __restrict__ fl_w2,
    const float* __restrict__ fl_b2, float* __restrict__ out)
{
    __shared__ __align__(16) float S[9088];
    __shared__ __align__(16) unsigned Wsm[3][1024];  // tf32 weight fragments, per-lane
    __shared__ float b2sm[32], ct2sm[32];

    float* xoT = S;             // [64][36]
    float* Bn  = S + 2304;      // [64][36]
    float* Tn  = S + 4608;      // [64][36]
    float* As  = S + 6912;      // [32][36]
    float* xls = S + 8064;      // [32][32]; gps alias after death
    float* gps = S + 8064;      // [32][32] gpool result tile

    const int tid = threadIdx.x;
    const int b = blockIdx.x >> 2, mt = blockIdx.x & 3;

    // ============== gpool: stage inputs + weight fragments ==============
    for (int i = tid; i < 2048; i += 128) {
        int c = i >> 6, n = i & 63;
        xoT[n * 36 + c] = x_object[(size_t)b * 2048 + i];
    }
    for (int i = tid; i < 1024; i += 128) {
        int c = i >> 5, ml = i & 31;
        xls[c * 32 + ml] = x_label[(size_t)b * 4096 + c * 128 + mt * 32 + ml];
    }
    // weight fragments: Wsm[s][(nt*32+lane)*8 + kt*2 + h]
    for (int i = tid; i < 3072; i += 128) {
        int s = i >> 10, r = i & 1023;
        int nt = r >> 8, ln = (r >> 3) & 31, idx = r & 7;
        int kt = idx >> 1, h = idx & 1;
        int g2 = ln >> 2, t2 = ln & 3;
        int no = 8 * nt + g2;
        int k0 = 8 * kt + t2 + 4 * h;
        float v;
        if (s == 0)      v = gw_w2[no * 32 + k0];
        else if (s == 1) v = gm_s1[no] * gm_w1[no * 35 + 3 + k0];
        else             v = gm_s2[no] * gm_w2[no * 32 + k0];
        Wsm[s][r] = f2tf(v);
    }
    if (tid < 32) { b2sm[tid] = gw_b2[tid]; ct2sm[tid] = gm_t2[tid]; }
    __syncthreads();

    // ============== gpool: precompute ==============
    for (int i = tid; i < 2048; i += 128) {
        int o = i >> 6, n = i & 63;
        float a = 0.f;
        #pragma unroll
        for (int c = 0; c < 32; c++) a += gw_w1[o * 32 + c] * xoT[n * 36 + c];
        Bn[n * 36 + o] = -gw_s[o] * a;
        const float* tx = template_xyz + (size_t)b * 192 + n * 3;
        Tn[n * 36 + o] = gm_s1[o] * (gm_w1[o * 35] * tx[0] + gm_w1[o * 35 + 1] * tx[1] +
                                     gm_w1[o * 35 + 2] * tx[2]) + gm_t1[o];
    }
    for (int i = tid; i < 1024; i += 128) {
        int o = i >> 5, ml = i & 31;
        float a = 0.f;
        #pragma unroll
        for (int c = 0; c < 32; c++) a += gw_w1[o * 32 + c] * xls[c * 32 + ml];
        As[ml * 36 + o] = gw_s[o] * a + gw_s[o] * gw_b1[o] + gw_t[o];
    }
    __syncthreads();   // As ready; xls dead -> gps region live

    const int w = tid >> 5, lane = tid & 31;
    const int g = lane >> 2, t = lane & 3;
    const int s1l = (lane & ~3) | (t >> 1);
    const int s2l = s1l + 2;
    const bool odd = (t & 1) != 0;

    const unsigned* w0p = &Wsm[0][lane * 8];
    const unsigned* w1p = &Wsm[1][lane * 8];
    const unsigned* w2p = &Wsm[2][lane * 8];

    // ============== gpool main loop (tf32 MMA cascade) ==============
    #pragma unroll 1
    for (int mi = 0; mi < 8; mi++) {
        const int ml = w * 8 + mi;
        float asv[8];
        #pragma unroll
        for (int kt = 0; kt < 4; kt++) {
            asv[2 * kt]     = As[ml * 36 + 8 * kt + t];
            asv[2 * kt + 1] = As[ml * 36 + 8 * kt + t + 4];
        }
        float mm[4][2];
        #pragma unroll
        for (int nt = 0; nt < 4; nt++) { mm[nt][0] = 0.f; mm[nt][1] = 0.f; }

        #pragma unroll 1
        for (int r = 0; r < 4; r++) {
            const int r0 = 16 * r + g, r1 = r0 + 8;

            unsigned ah[4][4];
            #pragma unroll
            for (int kt = 0; kt < 4; kt++) {
                int c0 = 8 * kt + t, c1 = c0 + 4;
                float x00 = asv[2 * kt]     + Bn[r0 * 36 + c0];
                float x10 = asv[2 * kt]     + Bn[r1 * 36 + c0];
                float x01 = asv[2 * kt + 1] + Bn[r0 * 36 + c1];
                float x11 = asv[2 * kt + 1] + Bn[r1 * 36 + c1];
                ah[kt][0] = f2tf(fmaxf(x00, 0.2f * x00));
                ah[kt][1] = f2tf(fmaxf(x10, 0.2f * x10));
                ah[kt][2] = f2tf(fmaxf(x01, 0.2f * x01));
                ah[kt][3] = f2tf(fmaxf(x11, 0.2f * x11));
            }

            // stage gw2 + sigmoid gate
            float dd[4][4];
            #pragma unroll
            for (int nt = 0; nt < 4; nt++) {
                uint4 wa = *(const uint4*)(w0p + nt * 256);
                uint4 wb = *(const uint4*)(w0p + nt * 256 + 4);
                float d0 = b2sm[8 * nt + 2 * t], d1 = b2sm[8 * nt + 2 * t + 1];
                float d2 = d0, d3 = d1;
                mma8(d0, d1, d2, d3, ah[0][0], ah[0][1], ah[0][2], ah[0][3], wa.x, wa.y);
                mma8(d0, d1, d2, d3, ah[1][0], ah[1][1], ah[1][2], ah[1][3], wa.z, wa.w);
                mma8(d0, d1, d2, d3, ah[2][0], ah[2][1], ah[2][2], ah[2][3], wb.x, wb.y);
                mma8(d0, d1, d2, d3, ah[3][0], ah[3][1], ah[3][2], ah[3][3], wb.z, wb.w);
                int o0 = 8 * nt + 2 * t;
                dd[nt][0] = __fdividef(xoT[r0 * 36 + o0],     1.f + __expf(-d0));
                dd[nt][1] = __fdividef(xoT[r0 * 36 + o0 + 1], 1.f + __expf(-d1));
                dd[nt][2] = __fdividef(xoT[r1 * 36 + o0],     1.f + __expf(-d2));
                dd[nt][3] = __fdividef(xoT[r1 * 36 + o0 + 1], 1.f + __expf(-d3));
            }

            // D->A transform
            #pragma unroll
            for (int j = 0; j < 4; j++) {
                float e0 = __shfl_sync(0xffffffffu, dd[j][0], s1l);
                float e1 = __shfl_sync(0xffffffffu, dd[j][1], s1l);
                float f0 = __shfl_sync(0xffffffffu, dd[j][0], s2l);
                float f1 = __shfl_sync(0xffffffffu, dd[j][1], s2l);
                float g0 = __shfl_sync(0xffffffffu, dd[j][2], s1l);
                float g1 = __shfl_sync(0xffffffffu, dd[j][3], s1l);
                float h0 = __shfl_sync(0xffffffffu, dd[j][2], s2l);
                float h1 = __shfl_sync(0xffffffffu, dd[j][3], s2l);
                ah[j][0] = f2tf(odd ? e1 : e0);
                ah[j][1] = f2tf(odd ? g1 : g0);
                ah[j][2] = f2tf(odd ? f1 : f0);
                ah[j][3] = f2tf(odd ? h1 : h0);
            }

            // stage gm1 + relu
            #pragma unroll
            for (int nt = 0; nt < 4; nt++) {
                uint4 wa = *(const uint4*)(w1p + nt * 256);
                uint4 wb = *(const uint4*)(w1p + nt * 256 + 4);
                int o0 = 8 * nt + 2 * t;
                float d0 = Tn[r0 * 36 + o0], d1 = Tn[r0 * 36 + o0 + 1];
                float d2 = Tn[r1 * 36 + o0], d3 = Tn[r1 * 36 + o0 + 1];
                mma8(d0, d1, d2, d3, ah[0][0], ah[0][1], ah[0][2], ah[0][3], wa.x, wa.y);
                mma8(d0, d1, d2, d3, ah[1][0], ah[1][1], ah[1][2], ah[1][3], wa.z, wa.w);
                mma8(d0, d1, d2, d3, ah[2][0], ah[2][1], ah[2][2], ah[2][3], wb.x, wb.y);
                mma8(d0, d1, d2, d3, ah[3][0], ah[3][1], ah[3][2], ah[3][3], wb.z, wb.w);
                dd[nt][0] = fmaxf(d0, 0.f); dd[nt][1] = fmaxf(d1, 0.f);
                dd[nt][2] = fmaxf(d2, 0.f); dd[nt][3] = fmaxf(d3, 0.f);
            }

            // D->A transform
            #pragma unroll
            for (int j = 0; j < 4; j++) {
                float e0 = __shfl_sync(0xffffffffu, dd[j][0], s1l);
                float e1 = __shfl_sync(0xffffffffu, dd[j][1], s1l);
                float f0 = __shfl_sync(0xffffffffu, dd[j][0], s2l);
                float f1 = __shfl_sync(0xffffffffu, dd[j][1], s2l);
                float g0 = __shfl_sync(0xffffffffu, dd[j][2], s1l);
                float g1 = __shfl_sync(0xffffffffu, dd[j][3], s1l);
                float h0 = __shfl_sync(0xffffffffu, dd[j][2], s2l);
                float h1 = __shfl_sync(0xffffffffu, dd[j][3], s2l);
                ah[j][0] = f2tf(odd ? e1 : e0);
                ah[j][1] = f2tf(odd ? g1 : g0);
                ah[j][2] = f2tf(odd ? f1 : f0);
                ah[j][3] = f2tf(odd ? h1 : h0);
            }

            // stage gm2 + relu/max fold
            #pragma unroll
            for (int nt = 0; nt < 4; nt++) {
                uint4 wa = *(const uint4*)(w2p + nt * 256);
                uint4 wb = *(const uint4*)(w2p + nt * 256 + 4);
                float d0 = ct2sm[8 * nt + 2 * t], d1 = ct2sm[8 * nt + 2 * t + 1];
                float d2 = d0, d3 = d1;
                mma8(d0, d1, d2, d3, ah[0][0], ah[0][1], ah[0][2], ah[0][3], wa.x, wa.y);
                mma8(d0, d1, d2, d3, ah[1][0], ah[1][1], ah[1][2], ah[1][3], wa.z, wa.w);
                mma8(d0, d1, d2, d3, ah[2][0], ah[2][1], ah[2][2], ah[2][3], wb.x, wb.y);
                mma8(d0, d1, d2, d3, ah[3][0], ah[3][1], ah[3][2], ah[3][3], wb.z, wb.w);
                mm[nt][0] = fmaxf(mm[nt][0], fmaxf(d0, d2));
                mm[nt][1] = fmaxf(mm[nt][1], fmaxf(d1, d3));
            }
        }

        #pragma unroll
        for (int nt = 0; nt < 4; nt++) {
            #pragma unroll
            for (int j = 0; j < 2; j++) {
                float v = mm[nt][j];
                v = fmaxf(v, __shfl_xor_sync(0xffffffffu, v, 4));
                v = fmaxf(v, __shfl_xor_sync(0xffffffffu, v, 8));
                v = fmaxf(v, __shfl_xor_sync(0xffffffffu, v, 16));
                mm[nt][j] = v;
            }
        }
        if (g == 0) {
            #pragma unroll
            for (int nt = 0; nt < 4; nt++) {
                int o0 = 8 * nt + 2 * t;
                gps[o0 * 32 + ml]       = mm[nt][0];
                gps[(o0 + 1) * 32 + ml] = mm[nt][1];
            }
        }
    }
    __syncthreads();   // gpool done; Bn/Tn/As dead

    // ============== k_out phase staging ==============
    float* w1T  = S + 2304;          // [68][32]
    float* w2T  = S + 4480;          // [32][32]
    float* na_s = S + 5504;          // [64]
    float* sb   = S + 5568;          // [4][32]
    int*   si   = (int*)(S + 5696);  // [4][32]
    float* hs   = S + 5824;          // [32][33]
    float* fuh2 = S + 6912;          // [32][33]
    float* o1s  = S + 2304;          // [64][33] over dead w1T

    for (int i = tid; i < 2176; i += 128) {
        int j = i >> 5, oo = i & 31;
        w1T[j * 32 + oo] = mlp_w1[oo * 68 + j];
    }
    for (int i = tid; i < 1024; i += 128) {
        int c = i >> 5, oo = i & 31;
        w2T[c * 32 + oo] = mlp_w2[oo * 32 + c];
    }
    if (tid < 64) {
        float s = 0.f;
        #pragma unroll
        for (int c = 0; c < 32; c++) { float v = xoT[tid * 36 + c]; s += v * v; }
        na_s[tid] = sqrtf(s);
    }

    const int ml = tid & 31, p = tid >> 5;
    const int m = mt * 32 + ml;

    float xl[32];
    #pragma unroll
    for (int c = 0; c < 32; c++)
        xl[c] = x_label[(size_t)b * 4096 + c * 128 + m];
    float nb = 0.f;
    #pragma unroll
    for (int c = 0; c < 32; c++) nb += xl[c] * xl[c];
    nb = sqrtf(nb);
    __syncthreads();

    // argmax (n split across 4 parts, first-max semantics preserved)
    float best = -3.4e38f; int bidx = 16 * p;
    #pragma unroll 1
    for (int n = 16 * p; n < 16 * p + 16; n++) {
        float num = 0.f;
        #pragma unroll
        for (int c = 0; c < 32; c++) num += xoT[n * 36 + c] * xl[c];
        float cs = num / fmaxf(na_s[n] * nb, 1e-8f);
        if (cs > best) { best = cs; bidx = n; }
    }
    sb[p * 32 + ml] = best; si[p * 32 + ml] = bidx;
    __syncthreads();
    best = sb[ml]; bidx = si[ml];
    #pragma unroll
    for (int pp = 1; pp < 4; pp++) {
        if (sb[pp * 32 + ml] > best) { best = sb[pp * 32 + ml]; bidx = si[pp * 32 + ml]; }
    }

    // MLP layer 1 (o in [8p, 8p+8))
    float hr[8];
    {
        const float* tx = template_xyz + (size_t)b * 192 + bidx * 3;
        float a0 = tx[0], a1 = tx[1], a2 = tx[2];
        #pragma unroll
        for (int oo = 0; oo < 8; oo++) {
            int oc = 8 * p + oo;
            hr[oo] = w1T[0 * 32 + oc] * best + w1T[1 * 32 + oc] * a0 +
                     w1T[2 * 32 + oc] * a1 + w1T[3 * 32 + oc] * a2;
        }
    }
    #pragma unroll
    for (int c = 0; c < 32; c++) {
        float xoc = xoT[bidx * 36 + c];
        #pragma unroll
        for (int oo = 0; oo < 8; oo++) hr[oo] += w1T[(4 + c) * 32 + 8 * p + oo] * xoc;
    }
    #pragma unroll
    for (int c = 0; c < 32; c++) {
        float v = xl[c];
        #pragma unroll
        for (int oo = 0; oo < 8; oo++) hr[oo] += w1T[(36 + c) * 32 + 8 * p + oo] * v;
    }
    #pragma unroll
    for (int oo = 0; oo < 8; oo++) {
        int oc = 8 * p + oo;
        hs[ml * 33 + oc] = fmaxf(mlp_s1[oc] * hr[oo] + mlp_t1[oc], 0.f);
    }
    __syncthreads();

    // MLP layer 2 -> fuh2
    float h2r[8] = {0.f, 0.f, 0.f, 0.f, 0.f, 0.f, 0.f, 0.f};
    #pragma unroll
    for (int c = 0; c < 32; c++) {
        float v = hs[ml * 33 + c];
        #pragma unroll
        for (int oo = 0; oo < 8; oo++) h2r[oo] += w2T[c * 32 + 8 * p + oo] * v;
    }
    #pragma unroll
    for (int oo = 0; oo < 8; oo++) {
        int oc = 8 * p + oo;
        fuh2[oc * 33 + ml] = fmaxf(mlp_s2[oc] * h2r[oo] + mlp_t2[oc], 0.f);
    }
    __syncthreads();

    // fl1 (o in [16p, 16p+16))
    float fv[64];
    #pragma unroll
    for (int c = 0; c < 32; c++) fv[c] = fuh2[c * 33 + ml];
    #pragma unroll
    for (int c = 0; c < 32; c++) fv[32 + c] = gps[c * 32 + ml];
    #pragma unroll 4
    for (int oo = 0; oo < 16; oo++) {
        int oc = 16 * p + oo;
        float acc = 0.f;
        const float4* wp4 = (const float4*)(fl_w1 + oc * 64);
        #pragma unroll
        for (int c4 = 0; c4 < 16; c4++) {
            float4 ww = __ldg(&wp4[c4]);
            acc += ww.x * fv[4 * c4] + ww.y * fv[4 * c4 + 1] +
                   ww.z * fv[4 * c4 + 2] + ww.w * fv[4 * c4 + 3];
        }
        o1s[oc * 33 + ml] = fmaxf(fl_s1[oc] * acc + fl_t1[oc], 0.f);
    }
    __syncthreads();

    // fl2
    float ov[64];
    #pragma unroll
    for (int c = 0; c < 64; c++) ov[c] = o1s[c * 33 + ml];
    #pragma unroll 4
    for (int oo = 0; oo < 16; oo++) {
        int oc = 16 * p + oo;
        float acc = fl_b2[oc];
        const float4* wp4 = (const float4*)(fl_w2 + oc * 64);
        #pragma unroll
        for (int c4 = 0; c4 < 16; c4++) {
            float4 ww = __ldg(&wp4[c4]);
            acc += ww.x * ov[4 * c4] + ww.y * ov[4 * c4 + 1] +
                   ww.z * ov[4 * c4 + 2] + ww.w * ov[4 * c4 + 3];
        }
        out[((size_t)b * 64 + oc) * NM + m] = acc;
    }
}

extern "C" void kernel_launch(void* const* d_in, const int* in_sizes, int n_in,
                              void* d_out, int out_size)
{
    const float* x_label      = (const float*)d_in[0];
    const float* x_object     = (const float*)d_in[1];
    const float* template_xyz = (const float*)d_in[2];
    const float* mlp_w1 = (const float*)d_in[3];
    const float* mlp_s1 = (const float*)d_in[4];
    const float* mlp_t1 = (const float*)d_in[5];
    const float* mlp_w2 = (const float*)d_in[6];
    const float* mlp_s2 = (const float*)d_in[7];
    const float* mlp_t2 = (const float*)d_in[8];
    const float* gw_w1  = (const float*)d_in[9];
    const float* gw_b1  = (const float*)d_in[10];
    const float* gw_s   = (const float*)d_in[11];
    const float* gw_t   = (const float*)d_in[12];
    const float* gw_w2  = (const float*)d_in[13];
    const float* gw_b2  = (const float*)d_in[14];
    const float* gm_w1  = (const float*)d_in[15];
    const float* gm_s1  = (const float*)d_in[16];
    const float* gm_t1  = (const float*)d_in[17];
    const float* gm_w2  = (const float*)d_in[18];
    const float* gm_s2  = (const float*)d_in[19];
    const float* gm_t2  = (const float*)d_in[20];
    const float* fl_w1  = (const float*)d_in[21];
    const float* fl_s1  = (const float*)d_in[22];
    const float* fl_t1  = (const float*)d_in[23];
    const float* fl_w2  = (const float*)d_in[24];
    const float* fl_b2  = (const float*)d_in[25];

    k_fused<<<512, 128>>>(x_label, x_object, template_xyz,
                          mlp_w1, mlp_s1, mlp_t1, mlp_w2, mlp_s2, mlp_t2,
                          gw_w1, gw_b1, gw_s, gw_t, gw_w2, gw_b2,
                          gm_w1, gm_s1, gm_t1, gm_w2, gm_s2, gm_t2,
                          fl_w1, fl_s1, fl_t1, fl_w2, fl_b2, (float*)d_out);
}

// round 17
// speedup vs baseline: 1.4481x; 1.4481x over previous
#include <cuda_runtime.h>

#define BB 128
#define NM 128

__device__ __forceinline__ unsigned f2tf(float x) {
    unsigned u; asm("cvt.rna.tf32.f32 %0, %1;" : "=r"(u) : "f"(x)); return u;
}
__device__ __forceinline__ void mma8(float& d0, float& d1, float& d2, float& d3,
                                     unsigned a0, unsigned a1, unsigned a2, unsigned a3,
                                     unsigned b0, unsigned b1) {
    asm("mma.sync.aligned.m16n8k8.row.col.f32.tf32.tf32.f32 "
        "{%0,%1,%2,%3},{%4,%5,%6,%7},{%8,%9},{%0,%1,%2,%3};"
        : "+f"(d0), "+f"(d1), "+f"(d2), "+f"(d3)
        : "r"(a0), "r"(a1), "r"(a2), "r"(a3), "r"(b0), "r"(b1));
}

// ---------------------------------------------------------------------------
// Fused kernel: R15 structure (weights in registers — best at 125.3us),
// with (1) biases moved to smem (frees 16 regs) and (2) the r-chunk loop
// unrolled 2x so two independent dependency chains software-pipeline.
// ---------------------------------------------------------------------------
__global__ __launch_bounds__(128) void k_fused(
    const float* __restrict__ x_label, const float* __restrict__ x_object,
    const float* __restrict__ template_xyz,
    const float* __restrict__ mlp_w1, const float* __restrict__ mlp_s1,
    const float* __restrict__ mlp_t1, const float* __restrict__ mlp_w2,
    const float* __restrict__ mlp_s2, const float* __restrict__ mlp_t2,
    const float* __restrict__ gw_w1, const float* __restrict__ gw_b1,
    const float* __restrict__ gw_s,  const float* __restrict__ gw_t,
    const float* __restrict__ gw_w2, const float* __restrict__ gw_b2,
    const float* __restrict__ gm_w1, const float* __restrict__ gm_s1,
    const float* __restrict__ gm_t1, const float* __restrict__ gm_w2,
    const float* __restrict__ gm_s2, const float* __restrict__ gm_t2,
    const float* __restrict__ fl_w1, const float* __restrict__ fl_s1,
    const float* __restrict__ fl_t1, const float* __restrict__ fl_w2,
    const float* __restrict__ fl_b2, float* __restrict__ out)
{
    __shared__ __align__(16) float S[9088];
    __shared__ float b2sm[32], ct2sm[32];

    float* xoT = S;             // [64][36]
    float* Bn  = S + 2304;      // [64][36]
    float* Tn  = S + 4608;      // [64][36]
    float* As  = S + 6912;      // [32][36]
    float* xls = S + 8064;      // [32][32]; gps alias after death
    float* gps = S + 8064;      // [32][32] gpool result tile

    const int tid = threadIdx.x;
    const int b = blockIdx.x >> 2, mt = blockIdx.x & 3;

    // ============== gpool: stage inputs ==============
    for (int i = tid; i < 2048; i += 128) {
        int c = i >> 6, n = i & 63;
        xoT[n * 36 + c] = x_object[(size_t)b * 2048 + i];
    }
    for (int i = tid; i < 1024; i += 128) {
        int c = i >> 5, ml = i & 31;
        xls[c * 32 + ml] = x_label[(size_t)b * 4096 + c * 128 + mt * 32 + ml];
    }
    if (tid < 32) { b2sm[tid] = gw_b2[tid]; ct2sm[tid] = gm_t2[tid]; }
    __syncthreads();

    // ============== gpool: precompute ==============
    for (int i = tid; i < 2048; i += 128) {
        int o = i >> 6, n = i & 63;
        float a = 0.f;
        #pragma unroll
        for (int c = 0; c < 32; c++) a += gw_w1[o * 32 + c] * xoT[n * 36 + c];
        Bn[n * 36 + o] = -gw_s[o] * a;
        const float* tx = template_xyz + (size_t)b * 192 + n * 3;
        Tn[n * 36 + o] = gm_s1[o] * (gm_w1[o * 35] * tx[0] + gm_w1[o * 35 + 1] * tx[1] +
                                     gm_w1[o * 35 + 2] * tx[2]) + gm_t1[o];
    }
    for (int i = tid; i < 1024; i += 128) {
        int o = i >> 5, ml = i & 31;
        float a = 0.f;
        #pragma unroll
        for (int c = 0; c < 32; c++) a += gw_w1[o * 32 + c] * xls[c * 32 + ml];
        As[ml * 36 + o] = gw_s[o] * a + gw_s[o] * gw_b1[o] + gw_t[o];
    }

    // ---- per-lane weight fragments (tf32, B col-major) ----
    const int w = tid >> 5, lane = tid & 31;
    const int g = lane >> 2, t = lane & 3;

    unsigned w0[4][4][2], w1f[4][4][2], w2f[4][4][2];
    #pragma unroll
    for (int nt = 0; nt < 4; nt++) {
        int no = 8 * nt + g;
        float s1v = gm_s1[no], s2v = gm_s2[no];
        #pragma unroll
        for (int kt = 0; kt < 4; kt++) {
            int k0 = 8 * kt + t;
            w0[kt][nt][0]  = f2tf(gw_w2[no * 32 + k0]);
            w0[kt][nt][1]  = f2tf(gw_w2[no * 32 + k0 + 4]);
            w1f[kt][nt][0] = f2tf(s1v * gm_w1[no * 35 + 3 + k0]);
            w1f[kt][nt][1] = f2tf(s1v * gm_w1[no * 35 + 3 + k0 + 4]);
            w2f[kt][nt][0] = f2tf(s2v * gm_w2[no * 32 + k0]);
            w2f[kt][nt][1] = f2tf(s2v * gm_w2[no * 32 + k0 + 4]);
        }
    }
    __syncthreads();   // As ready; xls dead -> gps region live

    const int s1l = (lane & ~3) | (t >> 1);
    const int s2l = s1l + 2;
    const bool odd = (t & 1) != 0;

    // ============== gpool main loop (tf32 MMA cascade) ==============
    #pragma unroll 1
    for (int mi = 0; mi < 8; mi++) {
        const int ml = w * 8 + mi;
        float asv[8];
        #pragma unroll
        for (int kt = 0; kt < 4; kt++) {
            asv[2 * kt]     = As[ml * 36 + 8 * kt + t];
            asv[2 * kt + 1] = As[ml * 36 + 8 * kt + t + 4];
        }
        float mm[4][2];
        #pragma unroll
        for (int nt = 0; nt < 4; nt++) { mm[nt][0] = 0.f; mm[nt][1] = 0.f; }

        #pragma unroll 2
        for (int r = 0; r < 4; r++) {
            const int r0 = 16 * r + g, r1 = r0 + 8;

            unsigned ah[4][4];
            #pragma unroll
            for (int kt = 0; kt < 4; kt++) {
                int c0 = 8 * kt + t, c1 = c0 + 4;
                float x00 = asv[2 * kt]     + Bn[r0 * 36 + c0];
                float x10 = asv[2 * kt]     + Bn[r1 * 36 + c0];
                float x01 = asv[2 * kt + 1] + Bn[r0 * 36 + c1];
                float x11 = asv[2 * kt + 1] + Bn[r1 * 36 + c1];
                ah[kt][0] = f2tf(fmaxf(x00, 0.2f * x00));
                ah[kt][1] = f2tf(fmaxf(x10, 0.2f * x10));
                ah[kt][2] = f2tf(fmaxf(x01, 0.2f * x01));
                ah[kt][3] = f2tf(fmaxf(x11, 0.2f * x11));
            }

            float dd[4][4];
            #pragma unroll
            for (int nt = 0; nt < 4; nt++) {
                float d0 = b2sm[8 * nt + 2 * t], d1 = b2sm[8 * nt + 2 * t + 1];
                float d2 = d0, d3 = d1;
                #pragma unroll
                for (int kt = 0; kt < 4; kt++) {
                    mma8(d0, d1, d2, d3, ah[kt][0], ah[kt][1], ah[kt][2], ah[kt][3],
                         w0[kt][nt][0], w0[kt][nt][1]);
                }
                int o0 = 8 * nt + 2 * t;
                dd[nt][0] = __fdividef(xoT[r0 * 36 + o0],     1.f + __expf(-d0));
                dd[nt][1] = __fdividef(xoT[r0 * 36 + o0 + 1], 1.f + __expf(-d1));
                dd[nt][2] = __fdividef(xoT[r1 * 36 + o0],     1.f + __expf(-d2));
                dd[nt][3] = __fdividef(xoT[r1 * 36 + o0 + 1], 1.f + __expf(-d3));
            }

            #pragma unroll
            for (int j = 0; j < 4; j++) {
                float e0 = __shfl_sync(0xffffffffu, dd[j][0], s1l);
                float e1 = __shfl_sync(0xffffffffu, dd[j][1], s1l);
                float f0 = __shfl_sync(0xffffffffu, dd[j][0], s2l);
                float f1 = __shfl_sync(0xffffffffu, dd[j][1], s2l);
                float g0 = __shfl_sync(0xffffffffu, dd[j][2], s1l);
                float g1 = __shfl_sync(0xffffffffu, dd[j][3], s1l);
                float h0 = __shfl_sync(0xffffffffu, dd[j][2], s2l);
                float h1 = __shfl_sync(0xffffffffu, dd[j][3], s2l);
                ah[j][0] = f2tf(odd ? e1 : e0);
                ah[j][1] = f2tf(odd ? g1 : g0);
                ah[j][2] = f2tf(odd ? f1 : f0);
                ah[j][3] = f2tf(odd ? h1 : h0);
            }

            #pragma unroll
            for (int nt = 0; nt < 4; nt++) {
                int o0 = 8 * nt + 2 * t;
                float d0 = Tn[r0 * 36 + o0], d1 = Tn[r0 * 36 + o0 + 1];
                float d2 = Tn[r1 * 36 + o0], d3 = Tn[r1 * 36 + o0 + 1];
                #pragma unroll
                for (int kt = 0; kt < 4; kt++) {
                    mma8(d0, d1, d2, d3, ah[kt][0], ah[kt][1], ah[kt][2], ah[kt][3],
                         w1f[kt][nt][0], w1f[kt][nt][1]);
                }
                dd[nt][0] = fmaxf(d0, 0.f); dd[nt][1] = fmaxf(d1, 0.f);
                dd[nt][2] = fmaxf(d2, 0.f); dd[nt][3] = fmaxf(d3, 0.f);
            }

            #pragma unroll
            for (int j = 0; j < 4; j++) {
                float e0 = __shfl_sync(0xffffffffu, dd[j][0], s1l);
                float e1 = __shfl_sync(0xffffffffu, dd[j][1], s1l);
                float f0 = __shfl_sync(0xffffffffu, dd[j][0], s2l);
                float f1 = __shfl_sync(0xffffffffu, dd[j][1], s2l);
                float g0 = __shfl_sync(0xffffffffu, dd[j][2], s1l);
                float g1 = __shfl_sync(0xffffffffu, dd[j][3], s1l);
                float h0 = __shfl_sync(0xffffffffu, dd[j][2], s2l);
                float h1 = __shfl_sync(0xffffffffu, dd[j][3], s2l);
                ah[j][0] = f2tf(odd ? e1 : e0);
                ah[j][1] = f2tf(odd ? g1 : g0);
                ah[j][2] = f2tf(odd ? f1 : f0);
                ah[j][3] = f2tf(odd ? h1 : h0);
            }

            #pragma unroll
            for (int nt = 0; nt < 4; nt++) {
                float d0 = ct2sm[8 * nt + 2 * t], d1 = ct2sm[8 * nt + 2 * t + 1];
                float d2 = d0, d3 = d1;
                #pragma unroll
                for (int kt = 0; kt < 4; kt++) {
                    mma8(d0, d1, d2, d3, ah[kt][0], ah[kt][1], ah[kt][2], ah[kt][3],
                         w2f[kt][nt][0], w2f[kt][nt][1]);
                }
                mm[nt][0] = fmaxf(mm[nt][0], fmaxf(d0, d2));
                mm[nt][1] = fmaxf(mm[nt][1], fmaxf(d1, d3));
            }
        }

        #pragma unroll
        for (int nt = 0; nt < 4; nt++) {
            #pragma unroll
            for (int j = 0; j < 2; j++) {
                float v = mm[nt][j];
                v = fmaxf(v, __shfl_xor_sync(0xffffffffu, v, 4));
                v = fmaxf(v, __shfl_xor_sync(0xffffffffu, v, 8));
                v = fmaxf(v, __shfl_xor_sync(0xffffffffu, v, 16));
                mm[nt][j] = v;
            }
        }
        if (g == 0) {
            #pragma unroll
            for (int nt = 0; nt < 4; nt++) {
                int o0 = 8 * nt + 2 * t;
                gps[o0 * 32 + ml]       = mm[nt][0];
                gps[(o0 + 1) * 32 + ml] = mm[nt][1];
            }
        }
    }
    __syncthreads();   // gpool done; Bn/Tn/As dead

    // ============== k_out phase staging ==============
    float* w1T  = S + 2304;          // [68][32]
    float* w2T  = S + 4480;          // [32][32]
    float* na_s = S + 5504;          // [64]
    float* sb   = S + 5568;          // [4][32]
    int*   si   = (int*)(S + 5696);  // [4][32]
    float* hs   = S + 5824;          // [32][33]
    float* fuh2 = S + 6912;          // [32][33]
    float* o1s  = S + 2304;          // [64][33] over dead w1T

    for (int i = tid; i < 2176; i += 128) {
        int j = i >> 5, oo = i & 31;
        w1T[j * 32 + oo] = mlp_w1[oo * 68 + j];
    }
    for (int i = tid; i < 1024; i += 128) {
        int c = i >> 5, oo = i & 31;
        w2T[c * 32 + oo] = mlp_w2[oo * 32 + c];
    }
    if (tid < 64) {
        float s = 0.f;
        #pragma unroll
        for (int c = 0; c < 32; c++) { float v = xoT[tid * 36 + c]; s += v * v; }
        na_s[tid] = sqrtf(s);
    }

    const int ml = tid & 31, p = tid >> 5;
    const int m = mt * 32 + ml;

    float xl[32];
    #pragma unroll
    for (int c = 0; c < 32; c++)
        xl[c] = x_label[(size_t)b * 4096 + c * 128 + m];
    float nb = 0.f;
    #pragma unroll
    for (int c = 0; c < 32; c++) nb += xl[c] * xl[c];
    nb = sqrtf(nb);
    __syncthreads();

    // argmax (n split across 4 parts, first-max semantics preserved)
    float best = -3.4e38f; int bidx = 16 * p;
    #pragma unroll 1
    for (int n = 16 * p; n < 16 * p + 16; n++) {
        float num = 0.f;
        #pragma unroll
        for (int c = 0; c < 32; c++) num += xoT[n * 36 + c] * xl[c];
        float cs = num / fmaxf(na_s[n] * nb, 1e-8f);
        if (cs > best) { best = cs; bidx = n; }
    }
    sb[p * 32 + ml] = best; si[p * 32 + ml] = bidx;
    __syncthreads();
    best = sb[ml]; bidx = si[ml];
    #pragma unroll
    for (int pp = 1; pp < 4; pp++) {
        if (sb[pp * 32 + ml] > best) { best = sb[pp * 32 + ml]; bidx = si[pp * 32 + ml]; }
    }

    // MLP layer 1 (o in [8p, 8p+8))
    float hr[8];
    {
        const float* tx = template_xyz + (size_t)b * 192 + bidx * 3;
        float a0 = tx[0], a1 = tx[1], a2 = tx[2];
        #pragma unroll
        for (int oo = 0; oo < 8; oo++) {
            int oc = 8 * p + oo;
            hr[oo] = w1T[0 * 32 + oc] * best + w1T[1 * 32 + oc] * a0 +
                     w1T[2 * 32 + oc] * a1 + w1T[3 * 32 + oc] * a2;
        }
    }
    #pragma unroll
    for (int c = 0; c < 32; c++) {
        float xoc = xoT[bidx * 36 + c];
        #pragma unroll
        for (int oo = 0; oo < 8; oo++) hr[oo] += w1T[(4 + c) * 32 + 8 * p + oo] * xoc;
    }
    #pragma unroll
    for (int c = 0; c < 32; c++) {
        float v = xl[c];
        #pragma unroll
        for (int oo = 0; oo < 8; oo++) hr[oo] += w1T[(36 + c) * 32 + 8 * p + oo] * v;
    }
    #pragma unroll
    for (int oo = 0; oo < 8; oo++) {
        int oc = 8 * p + oo;
        hs[ml * 33 + oc] = fmaxf(mlp_s1[oc] * hr[oo] + mlp_t1[oc], 0.f);
    }
    __syncthreads();

    // MLP layer 2 -> fuh2
    float h2r[8] = {0.f, 0.f, 0.f, 0.f, 0.f, 0.f, 0.f, 0.f};
    #pragma unroll
    for (int c = 0; c < 32; c++) {
        float v = hs[ml * 33 + c];
        #pragma unroll
        for (int oo = 0; oo < 8; oo++) h2r[oo] += w2T[c * 32 + 8 * p + oo] * v;
    }
    #pragma unroll
    for (int oo = 0; oo < 8; oo++) {
        int oc = 8 * p + oo;
        fuh2[oc * 33 + ml] = fmaxf(mlp_s2[oc] * h2r[oo] + mlp_t2[oc], 0.f);
    }
    __syncthreads();

    // fl1 (o in [16p, 16p+16))
    float fv[64];
    #pragma unroll
    for (int c = 0; c < 32; c++) fv[c] = fuh2[c * 33 + ml];
    #pragma unroll
    for (int c = 0; c < 32; c++) fv[32 + c] = gps[c * 32 + ml];
    #pragma unroll 4
    for (int oo = 0; oo < 16; oo++) {
        int oc = 16 * p + oo;
        float acc = 0.f;
        const float4* wp4 = (const float4*)(fl_w1 + oc * 64);
        #pragma unroll
        for (int c4 = 0; c4 < 16; c4++) {
            float4 ww = __ldg(&wp4[c4]);
            acc += ww.x * fv[4 * c4] + ww.y * fv[4 * c4 + 1] +
                   ww.z * fv[4 * c4 + 2] + ww.w * fv[4 * c4 + 3];
        }
        o1s[oc * 33 + ml] = fmaxf(fl_s1[oc] * acc + fl_t1[oc], 0.f);
    }
    __syncthreads();

    // fl2
    float ov[64];
    #pragma unroll
    for (int c = 0; c < 64; c++) ov[c] = o1s[c * 33 + ml];
    #pragma unroll 4
    for (int oo = 0; oo < 16; oo++) {
        int oc = 16 * p + oo;
        float acc = fl_b2[oc];
        const float4* wp4 = (const float4*)(fl_w2 + oc * 64);
        #pragma unroll
        for (int c4 = 0; c4 < 16; c4++) {
            float4 ww = __ldg(&wp4[c4]);
            acc += ww.x * ov[4 * c4] + ww.y * ov[4 * c4 + 1] +
                   ww.z * ov[4 * c4 + 2] + ww.w * ov[4 * c4 + 3];
        }
        out[((size_t)b * 64 + oc) * NM + m] = acc;
    }
}

extern "C" void kernel_launch(void* const* d_in, const int* in_sizes, int n_in,
                              void* d_out, int out_size)
{
    const float* x_label      = (const float*)d_in[0];
    const float* x_object     = (const float*)d_in[1];
    const float* template_xyz = (const float*)d_in[2];
    const float* mlp_w1 = (const float*)d_in[3];
    const float* mlp_s1 = (const float*)d_in[4];
    const float* mlp_t1 = (const float*)d_in[5];
    const float* mlp_w2 = (const float*)d_in[6];
    const float* mlp_s2 = (const float*)d_in[7];
    const float* mlp_t2 = (const float*)d_in[8];
    const float* gw_w1  = (const float*)d_in[9];
    const float* gw_b1  = (const float*)d_in[10];
    const float* gw_s   = (const float*)d_in[11];
    const float* gw_t   = (const float*)d_in[12];
    const float* gw_w2  = (const float*)d_in[13];
    const float* gw_b2  = (const float*)d_in[14];
    const float* gm_w1  = (const float*)d_in[15];
    const float* gm_s1  = (const float*)d_in[16];
    const float* gm_t1  = (const float*)d_in[17];
    const float* gm_w2  = (const float*)d_in[18];
    const float* gm_s2  = (const float*)d_in[19];
    const float* gm_t2  = (const float*)d_in[20];
    const float* fl_w1  = (const float*)d_in[21];
    const float* fl_s1  = (const float*)d_in[22];
    const float* fl_t1  = (const float*)d_in[23];
    const float* fl_w2  = (const float*)d_in[24];
    const float* fl_b2  = (const float*)d_in[25];

    k_fused<<<512, 128>>>(x_label, x_object, template_xyz,
                          mlp_w1, mlp_s1, mlp_t1, mlp_w2, mlp_s2, mlp_t2,
                          gw_w1, gw_b1, gw_s, gw_t, gw_w2, gw_b2,
                          gm_w1, gm_s1, gm_t1, gm_w2, gm_s2, gm_t2,
                          fl_w1, fl_s1, fl_t1, fl_w2, fl_b2, (float*)d_out);
}